// round 15
// baseline (speedup 1.0000x reference)
#include <cuda_runtime.h>
#include <cuda_fp16.h>
#include <stdint.h>

// ---------------- static geometry ----------------
#define Bb   2
#define Ss   4096
#define Dd   2048
#define Hh   32
#define HDd  64
#define NTH  8
#define NTW  4

#define MM   (Bb*Ss)  // 8192
#define DD   ((size_t)Dd * Dd)

// ---------------- scratch (fp16) ----------------
__device__ __half g_Qh[(size_t)MM * Dd];
__device__ __half g_Kh[(size_t)MM * Dd];
__device__ __half g_Vh[(size_t)MM * Dd];
__device__ __half g_Oh[(size_t)MM * Dd];
__device__ __half g_Xh[(size_t)MM * Dd];
__device__ __half g_Wh[4 * DD];          // transposed fp16 weights [N][K]

// ---------------- helpers ----------------
__device__ __forceinline__ uint32_t smem_u32(const void* p) {
    uint32_t a;
    asm("{ .reg .u64 t; cvta.to.shared.u64 t, %1; cvt.u32.u64 %0, t; }"
        : "=r"(a) : "l"(p));
    return a;
}
__device__ __forceinline__ void cp16(uint32_t dst, const void* src) {
    asm volatile("cp.async.cg.shared.global [%0], [%1], 16;"
                 :: "r"(dst), "l"(src) : "memory");
}
__device__ __forceinline__ void cp_commit() {
    asm volatile("cp.async.commit_group;" ::: "memory");
}
template<int N>
__device__ __forceinline__ void cp_wait() {
    asm volatile("cp.async.wait_group %0;" :: "n"(N) : "memory");
}
__device__ __forceinline__ uint32_t packh2(float a, float b) {
    __half2 h = __floats2half2_rn(a, b);
    return *reinterpret_cast<uint32_t*>(&h);
}

#define LDSM_X4(r0, r1, r2, r3, addr) \
    asm volatile("ldmatrix.sync.aligned.m8n8.x4.shared.b16 {%0,%1,%2,%3}, [%4];" \
                 : "=r"(r0), "=r"(r1), "=r"(r2), "=r"(r3) : "r"(addr))
#define LDSM_X4_T(r0, r1, r2, r3, addr) \
    asm volatile("ldmatrix.sync.aligned.m8n8.x4.trans.shared.b16 {%0,%1,%2,%3}, [%4];" \
                 : "=r"(r0), "=r"(r1), "=r"(r2), "=r"(r3) : "r"(addr))
#define HMMA16(acc, a, b0, b1) \
    asm volatile("mma.sync.aligned.m16n8k16.row.col.f32.f16.f16.f32 " \
                 "{%0,%1,%2,%3},{%4,%5,%6,%7},{%8,%9},{%0,%1,%2,%3};" \
                 : "+f"(acc[0]), "+f"(acc[1]), "+f"(acc[2]), "+f"(acc[3]) \
                 : "r"(a[0]), "r"(a[1]), "r"(a[2]), "r"(a[3]), "r"(b0), "r"(b1))

// ---------------- merged prep kernel ----------------
// z = 0..3: transpose+cvt W[z] into Wh[z]; z = 4: cvt X -> fp16
__global__ __launch_bounds__(256) void prep_kernel(
    const float4* __restrict__ X4,
    const float* __restrict__ W0, const float* __restrict__ W1,
    const float* __restrict__ W2, const float* __restrict__ W3,
    __half* __restrict__ Wh, uint2* __restrict__ Xh)
{
    const int z = blockIdx.z;
    if (z == 4) {
        // X convert: 4096 blocks cover 64x64 grid; flatten
        int blk = blockIdx.y * 64 + blockIdx.x;
        int base = blk * 1024 + (threadIdx.y * 32 + threadIdx.x);
#pragma unroll
        for (int i = 0; i < 4; i++) {
            int idx = base + i * 256;
            float4 v = X4[idx];
            Xh[idx] = make_uint2(packh2(v.x, v.y), packh2(v.z, v.w));
        }
        return;
    }
    __shared__ float t[32][33];
    const float* W = (z == 0) ? W0 : (z == 1) ? W1 : (z == 2) ? W2 : W3;
    __half* dst = Wh + (size_t)z * DD;
    const int bx = blockIdx.x * 32;  // n
    const int by = blockIdx.y * 32;  // k
    const int tx = threadIdx.x, ty = threadIdx.y;
#pragma unroll
    for (int r = 0; r < 32; r += 8)
        t[ty + r][tx] = W[(size_t)(by + ty + r) * Dd + bx + tx];
    __syncthreads();
#pragma unroll
    for (int r = 0; r < 32; r += 8)
        dst[(size_t)(bx + ty + r) * Dd + by + tx] = __float2half_rn(t[tx][ty + r]);
}

// ---------------- fp16 GEMM: C[M,2048] = A[M,2048] @ Wt^T (frozen) ----------------
#define GBK 64
#define AST (128 * GBK * 2)      // 16384 B per operand
#define STB (2 * AST)            // 32768 B per stage
#define NST 3
#define SMEMT (NST * STB)        // 98304 B

__device__ __forceinline__ void hfill(
    const __half* __restrict__ A, const __half* __restrict__ Bt,
    uint32_t sbase, int stage, int m0, int n0, int k0, int tid)
{
    const uint32_t sA = sbase + stage * STB;
    const uint32_t sB = sA + AST;
#pragma unroll
    for (int i = 0; i < 4; i++) {
        int idx = tid + i * 256;
        int row = idx >> 3;
        int c   = idx & 7;
        uint32_t phys = row * 128 + ((c ^ (row & 7)) << 4);
        cp16(sA + phys, A + (size_t)(m0 + row) * Dd + k0 + c * 8);
    }
#pragma unroll
    for (int i = 0; i < 4; i++) {
        int idx = tid + i * 256;
        int row = idx >> 3;
        int c   = idx & 7;
        uint32_t phys = row * 128 + ((c ^ (row & 7)) << 4);
        cp16(sB + phys, Bt + (size_t)(n0 + row) * Dd + k0 + c * 8);
    }
}

__global__ __launch_bounds__(256, 2) void hgemm_kernel(
    const __half* __restrict__ A, const __half* __restrict__ Wh,
    void* C0, void* C1, void* C2, int out_f32)
{
    extern __shared__ char smem[];
    const uint32_t sbase = smem_u32(smem);
    const int tid  = threadIdx.x;
    const int wid  = tid >> 5;
    const int lane = tid & 31;
    const int g    = lane >> 2;
    const int t    = lane & 3;
    const int n0 = blockIdx.x * 128;
    const int m0 = blockIdx.y * 128;
    const int z  = blockIdx.z;

    const __half* Bt = Wh + (size_t)z * DD;
    void* Cv = (z == 0) ? C0 : ((z == 1) ? C1 : C2);

    const int warp_m = (wid & 3) * 32;
    const int warp_n = (wid >> 2) * 64;

    float acc[2][8][4];
#pragma unroll
    for (int i = 0; i < 2; i++)
#pragma unroll
        for (int j = 0; j < 8; j++)
#pragma unroll
            for (int c = 0; c < 4; c++) acc[i][j][c] = 0.f;

    hfill(A, Bt, sbase, 0, m0, n0, 0, tid);
    cp_commit();
    hfill(A, Bt, sbase, 1, m0, n0, GBK, tid);
    cp_commit();

    const int NCH = Dd / GBK;  // 32
    const int lrow_a = ((lane >> 3) & 1) * 8 + (lane & 7);
    const int lchk_a = (lane >> 4);
    const int lrow_b = ((lane >> 4) << 3) + (lane & 7);
    const int lchk_b = ((lane >> 3) & 1);

    for (int ch = 0; ch < NCH; ch++) {
        if (ch < NCH - 1) cp_wait<1>(); else cp_wait<0>();
        __syncthreads();

        if (ch + 2 < NCH) {
            hfill(A, Bt, sbase, (ch + 2) % NST, m0, n0, (ch + 2) * GBK, tid);
            cp_commit();
        }

        const uint32_t sA = sbase + (ch % NST) * STB;
        const uint32_t sB = sA + AST;

#pragma unroll
        for (int ks = 0; ks < 4; ks++) {
            const int c0 = ks * 2;

            uint32_t af[2][4];
#pragma unroll
            for (int wm = 0; wm < 2; wm++) {
                int row = warp_m + wm * 16 + lrow_a;
                int chk = c0 + lchk_a;
                uint32_t addr = sA + row * 128 + ((chk ^ (row & 7)) << 4);
                LDSM_X4(af[wm][0], af[wm][1], af[wm][2], af[wm][3], addr);
            }
#pragma unroll
            for (int p = 0; p < 4; p++) {
                int row = warp_n + p * 16 + lrow_b;
                int chk = c0 + lchk_b;
                uint32_t addr = sB + row * 128 + ((chk ^ (row & 7)) << 4);
                uint32_t b0, b1, b2, b3;
                LDSM_X4(b0, b1, b2, b3, addr);
#pragma unroll
                for (int wm = 0; wm < 2; wm++) {
                    HMMA16(acc[wm][2 * p],     af[wm], b0, b1);
                    HMMA16(acc[wm][2 * p + 1], af[wm], b2, b3);
                }
            }
        }
    }

    // ---- epilogue: smem-staged, fully coalesced 16B stores ----
    __syncthreads();
    if (out_f32) {
        float* stg = reinterpret_cast<float*>(smem);
#pragma unroll
        for (int wm = 0; wm < 2; wm++) {
            const int r0 = warp_m + wm * 16 + g;
#pragma unroll
            for (int wn = 0; wn < 8; wn++) {
                const int c = warp_n + wn * 8 + 2 * t;
                *reinterpret_cast<float2*>(&stg[r0 * 136 + c]) =
                    make_float2(acc[wm][wn][0], acc[wm][wn][1]);
                *reinterpret_cast<float2*>(&stg[(r0 + 8) * 136 + c]) =
                    make_float2(acc[wm][wn][2], acc[wm][wn][3]);
            }
        }
        __syncthreads();
        float* C = (float*)Cv;
#pragma unroll
        for (int i = 0; i < 16; i++) {
            int idx = tid + i * 256;
            int row = idx >> 5;
            int chk = idx & 31;
            uint4 v = *reinterpret_cast<const uint4*>(&stg[row * 136 + chk * 4]);
            *reinterpret_cast<uint4*>(&C[(size_t)(m0 + row) * Dd + n0 + chk * 4]) = v;
        }
    } else {
        __half* stg = reinterpret_cast<__half*>(smem);
#pragma unroll
        for (int wm = 0; wm < 2; wm++) {
            const int r0 = warp_m + wm * 16 + g;
#pragma unroll
            for (int wn = 0; wn < 8; wn++) {
                const int c = warp_n + wn * 8 + 2 * t;
                *reinterpret_cast<uint32_t*>(&stg[r0 * 136 + c]) =
                    packh2(acc[wm][wn][0], acc[wm][wn][1]);
                *reinterpret_cast<uint32_t*>(&stg[(r0 + 8) * 136 + c]) =
                    packh2(acc[wm][wn][2], acc[wm][wn][3]);
            }
        }
        __syncthreads();
        __half* C = (__half*)Cv;
#pragma unroll
        for (int i = 0; i < 8; i++) {
            int idx = tid + i * 256;
            int row = idx >> 4;
            int chk = idx & 15;
            uint4 v = *reinterpret_cast<const uint4*>(&stg[row * 136 + chk * 8]);
            *reinterpret_cast<uint4*>(&C[(size_t)(m0 + row) * Dd + n0 + chk * 8]) = v;
        }
    }
}

// ---------------- fp16 attention: 4 warps x 32 queries, 128-token chunks ----------------
// K/V ldsm fragments shared across 2 m-tiles per warp -> half the smem traffic.
#define AKS128  16384
#define AKST128 (2 * AKS128)     // 32 KB per stage
#define ASMEM   (2 * AKST128)    // 64 KB

__device__ __forceinline__ void afill128(
    const __half* __restrict__ K, const __half* __restrict__ V,
    uint32_t sbase, int stage, int b, int h, int kth, int ktw, int tid)
{
    const uint32_t sK = sbase + stage * AKST128;
    const uint32_t sV = sK + AKS128;
#pragma unroll
    for (int i = 0; i < 8; i++) {
        int idx = tid + i * 128;    // 0..1023
        int row = idx >> 3;         // token 0..127
        int c   = idx & 7;          // 16B chunk of hd
        int rr  = row >> 4;
        int cc  = row & 15;
        int skv = (kth * 8 + rr) * 64 + (ktw * 16 + cc);
        size_t gaddr = ((size_t)(b * Ss + skv)) * Dd + h * HDd + c * 8;
        uint32_t phys = row * 128 + ((c ^ (row & 7)) << 4);
        cp16(sK + phys, K + gaddr);
        cp16(sV + phys, V + gaddr);
    }
}

__global__ __launch_bounds__(128, 2) void attn_h_kernel(
    const __half* __restrict__ Q, const __half* __restrict__ Kh,
    const __half* __restrict__ Vh, __half* __restrict__ O)
{
    extern __shared__ char asmem[];
    const uint32_t sbase = smem_u32(asmem);

    const int tile = blockIdx.x;
    const int h    = blockIdx.y;
    const int b    = blockIdx.z;
    const int tid  = threadIdx.x;
    const int wid  = tid >> 5;
    const int lane = tid & 31;
    const int g    = lane >> 2;
    const int tg   = lane & 3;

    const int th_i = tile >> 2;
    const int tw_i = tile & 3;

    const int chc = min(max(th_i, 1), NTH - 1);
    const int cwc = min(max(tw_i, 1), NTW - 1);
    int kvt[4];
    kvt[0] = (chc - 1) * NTW + (cwc - 1);
    kvt[1] = (chc - 1) * NTW + cwc;
    kvt[2] = chc * NTW + (cwc - 1);
    kvt[3] = chc * NTW + cwc;

    // prologue fill (tile 0) first, so Q loads overlap it
    afill128(Kh, Vh, sbase, 0, b, h, kvt[0] >> 2, kvt[0] & 3, tid);
    cp_commit();

    // warp owns 32 queries = two m16 tiles
    size_t qrow[2][2];
#pragma unroll
    for (int mt = 0; mt < 2; mt++) {
        int qi0 = wid * 32 + mt * 16 + g;
        int qi1 = qi0 + 8;
        int sq0 = (th_i * 8 + (qi0 >> 4)) * 64 + tw_i * 16 + (qi0 & 15);
        int sq1 = (th_i * 8 + (qi1 >> 4)) * 64 + tw_i * 16 + (qi1 & 15);
        qrow[mt][0] = ((size_t)(b * Ss + sq0)) * Dd + h * HDd;
        qrow[mt][1] = ((size_t)(b * Ss + sq1)) * Dd + h * HDd;
    }

    const __half2 qscale = __floats2half2_rn(0.125f, 0.125f);
    uint32_t qa[2][4][4];
#pragma unroll
    for (int mt = 0; mt < 2; mt++)
#pragma unroll
        for (int ks = 0; ks < 4; ks++) {
            int kb = ks * 16;
            __half2 v0 = *reinterpret_cast<const __half2*>(&Q[qrow[mt][0] + kb + 2 * tg]);
            __half2 v1 = *reinterpret_cast<const __half2*>(&Q[qrow[mt][1] + kb + 2 * tg]);
            __half2 v2 = *reinterpret_cast<const __half2*>(&Q[qrow[mt][0] + kb + 8 + 2 * tg]);
            __half2 v3 = *reinterpret_cast<const __half2*>(&Q[qrow[mt][1] + kb + 8 + 2 * tg]);
            v0 = __hmul2(v0, qscale); v1 = __hmul2(v1, qscale);
            v2 = __hmul2(v2, qscale); v3 = __hmul2(v3, qscale);
            qa[mt][ks][0] = *reinterpret_cast<uint32_t*>(&v0);
            qa[mt][ks][1] = *reinterpret_cast<uint32_t*>(&v1);
            qa[mt][ks][2] = *reinterpret_cast<uint32_t*>(&v2);
            qa[mt][ks][3] = *reinterpret_cast<uint32_t*>(&v3);
        }

    float oacc[2][8][4];
#pragma unroll
    for (int mt = 0; mt < 2; mt++)
#pragma unroll
        for (int j = 0; j < 8; j++)
#pragma unroll
            for (int c = 0; c < 4; c++) oacc[mt][j][c] = 0.f;
    float lacc[2][4] = {{0.f,0.f,0.f,0.f},{0.f,0.f,0.f,0.f}};
    const uint32_t ones2 = 0x3C003C00u;

    const int lrow_b = ((lane >> 4) << 3) + (lane & 7);
    const int lchk_b = ((lane >> 3) & 1);
    const int lrow_v = ((lane >> 3) & 1) * 8 + (lane & 7);
    const int lchk_v = (lane >> 4);
    const float L2E = 1.4426950408889634f;

    for (int c4 = 0; c4 < 4; c4++) {
        cp_wait<0>();
        __syncthreads();

        if (c4 + 1 < 4) {
            int kt = kvt[c4 + 1];
            afill128(Kh, Vh, sbase, (c4 + 1) & 1, b, h, kt >> 2, kt & 3, tid);
            cp_commit();
        }

        const uint32_t sK = sbase + (c4 & 1) * AKST128;
        const uint32_t sV = sK + AKS128;

#pragma unroll
        for (int h2 = 0; h2 < 2; h2++) {
            const int rb = h2 * 64;

            // ---- S = Q K^T over keys [rb, rb+64), both m-tiles per K fragment ----
            float sacc[2][8][4];
#pragma unroll
            for (int mt = 0; mt < 2; mt++)
#pragma unroll
                for (int j = 0; j < 8; j++)
#pragma unroll
                    for (int c = 0; c < 4; c++) sacc[mt][j][c] = 0.f;

#pragma unroll
            for (int ks = 0; ks < 4; ks++) {
                const int c0 = ks * 2;
#pragma unroll
                for (int p = 0; p < 4; p++) {
                    int row = rb + p * 16 + lrow_b;
                    int chk = c0 + lchk_b;
                    uint32_t addr = sK + row * 128 + ((chk ^ (row & 7)) << 4);
                    uint32_t k0, k1, k2, k3;
                    LDSM_X4(k0, k1, k2, k3, addr);
#pragma unroll
                    for (int mt = 0; mt < 2; mt++) {
                        HMMA16(sacc[mt][2 * p],     qa[mt][ks], k0, k1);
                        HMMA16(sacc[mt][2 * p + 1], qa[mt][ks], k2, k3);
                    }
                }
            }

            // ---- p = exp(s) via f16x2 ex2; l via P @ ones HMMA ----
            uint32_t pa[2][4][4];
#pragma unroll
            for (int mt = 0; mt < 2; mt++)
#pragma unroll
                for (int mI = 0; mI < 4; mI++) {
                    pa[mt][mI][0] = packh2(sacc[mt][2 * mI][0] * L2E,     sacc[mt][2 * mI][1] * L2E);
                    pa[mt][mI][1] = packh2(sacc[mt][2 * mI][2] * L2E,     sacc[mt][2 * mI][3] * L2E);
                    pa[mt][mI][2] = packh2(sacc[mt][2 * mI + 1][0] * L2E, sacc[mt][2 * mI + 1][1] * L2E);
                    pa[mt][mI][3] = packh2(sacc[mt][2 * mI + 1][2] * L2E, sacc[mt][2 * mI + 1][3] * L2E);
                    asm("ex2.approx.f16x2 %0, %0;" : "+r"(pa[mt][mI][0]));
                    asm("ex2.approx.f16x2 %0, %0;" : "+r"(pa[mt][mI][1]));
                    asm("ex2.approx.f16x2 %0, %0;" : "+r"(pa[mt][mI][2]));
                    asm("ex2.approx.f16x2 %0, %0;" : "+r"(pa[mt][mI][3]));
                    HMMA16(lacc[mt], pa[mt][mI], ones2, ones2);
                }

            // ---- O += P V, both m-tiles per V fragment ----
#pragma unroll
            for (int mI = 0; mI < 4; mI++) {
                const int kb = rb + mI * 16;
#pragma unroll
                for (int p = 0; p < 4; p++) {
                    int row = kb + lrow_v;
                    int chk = 2 * p + lchk_v;
                    uint32_t addr = sV + row * 128 + ((chk ^ (row & 7)) << 4);
                    uint32_t v0, v1, v2, v3;
                    LDSM_X4_T(v0, v1, v2, v3, addr);
#pragma unroll
                    for (int mt = 0; mt < 2; mt++) {
                        HMMA16(oacc[mt][2 * p],     pa[mt][mI], v0, v1);
                        HMMA16(oacc[mt][2 * p + 1], pa[mt][mI], v2, v3);
                    }
                }
            }
        }
    }

    // ---- epilogue ----
#pragma unroll
    for (int mt = 0; mt < 2; mt++) {
        const float inv0 = 1.f / lacc[mt][0];
        const float inv1 = 1.f / lacc[mt][2];
#pragma unroll
        for (int jn = 0; jn < 8; jn++) {
            int vd = 8 * jn + 2 * tg;
            *reinterpret_cast<uint32_t*>(&O[qrow[mt][0] + vd]) =
                packh2(oacc[mt][jn][0] * inv0, oacc[mt][jn][1] * inv0);
            *reinterpret_cast<uint32_t*>(&O[qrow[mt][1] + vd]) =
                packh2(oacc[mt][jn][2] * inv1, oacc[mt][jn][3] * inv1);
        }
    }
}

// ---------------- launch ----------------
extern "C" void kernel_launch(void* const* d_in, const int* in_sizes, int n_in,
                              void* d_out, int out_size)
{
    const float* X  = (const float*)d_in[0];
    const float* Wq = (const float*)d_in[1];
    const float* Wk = (const float*)d_in[2];
    const float* Wv = (const float*)d_in[3];
    const float* Wo = (const float*)d_in[4];
    float* out = (float*)d_out;

    __half *Qh, *Kh, *Vh, *Oh, *Xh, *Wh;
    cudaGetSymbolAddress((void**)&Qh, g_Qh);
    cudaGetSymbolAddress((void**)&Kh, g_Kh);
    cudaGetSymbolAddress((void**)&Vh, g_Vh);
    cudaGetSymbolAddress((void**)&Oh, g_Oh);
    cudaGetSymbolAddress((void**)&Xh, g_Xh);
    cudaGetSymbolAddress((void**)&Wh, g_Wh);

    cudaFuncSetAttribute(hgemm_kernel,
                         cudaFuncAttributeMaxDynamicSharedMemorySize, SMEMT);
    cudaFuncSetAttribute(attn_h_kernel,
                         cudaFuncAttributeMaxDynamicSharedMemorySize, ASMEM);

    // merged prep: 4 weight transposes + X convert in one launch
    dim3 tb(32, 8), tg5(64, 64, 5);
    prep_kernel<<<tg5, tb>>>((const float4*)X, Wq, Wk, Wv, Wo, Wh, (uint2*)Xh);

    // fused Q/K/V projections (fp16 out)
    dim3 gq(Dd / 128, MM / 128, 3);
    hgemm_kernel<<<gq, 256, SMEMT>>>(Xh, Wh, Qh, Kh, Vh, 0);

    dim3 ga(32, Hh, Bb);
    attn_h_kernel<<<ga, 128, ASMEM>>>(Qh, Kh, Vh, Oh);

    // output projection (fp32 out)
    dim3 gg(Dd / 128, MM / 128, 1);
    hgemm_kernel<<<gg, 256, SMEMT>>>(Oh, Wh + 3 * DD, out, out, out, 1);
}

// round 16
// speedup vs baseline: 1.0087x; 1.0087x over previous
#include <cuda_runtime.h>
#include <cuda_fp16.h>
#include <stdint.h>

// ---------------- static geometry ----------------
#define Bb   2
#define Ss   4096
#define Dd   2048
#define Hh   32
#define HDd  64
#define NTH  8
#define NTW  4

#define MM   (Bb*Ss)  // 8192
#define DD   ((size_t)Dd * Dd)

// ---------------- scratch (fp16) ----------------
__device__ __half g_Qh[(size_t)MM * Dd];
__device__ __half g_Kh[(size_t)MM * Dd];
__device__ __half g_Vh[(size_t)MM * Dd];
__device__ __half g_Oh[(size_t)MM * Dd];
__device__ __half g_Xh[(size_t)MM * Dd];
__device__ __half g_Wh[4 * DD];          // transposed fp16 weights [N][K]

// ---------------- helpers ----------------
__device__ __forceinline__ uint32_t smem_u32(const void* p) {
    uint32_t a;
    asm("{ .reg .u64 t; cvta.to.shared.u64 t, %1; cvt.u32.u64 %0, t; }"
        : "=r"(a) : "l"(p));
    return a;
}
__device__ __forceinline__ void cp16(uint32_t dst, const void* src) {
    asm volatile("cp.async.cg.shared.global [%0], [%1], 16;"
                 :: "r"(dst), "l"(src) : "memory");
}
__device__ __forceinline__ void cp_commit() {
    asm volatile("cp.async.commit_group;" ::: "memory");
}
template<int N>
__device__ __forceinline__ void cp_wait() {
    asm volatile("cp.async.wait_group %0;" :: "n"(N) : "memory");
}
__device__ __forceinline__ uint32_t packh2(float a, float b) {
    __half2 h = __floats2half2_rn(a, b);
    return *reinterpret_cast<uint32_t*>(&h);
}

#define LDSM_X4(r0, r1, r2, r3, addr) \
    asm volatile("ldmatrix.sync.aligned.m8n8.x4.shared.b16 {%0,%1,%2,%3}, [%4];" \
                 : "=r"(r0), "=r"(r1), "=r"(r2), "=r"(r3) : "r"(addr))
#define LDSM_X4_T(r0, r1, r2, r3, addr) \
    asm volatile("ldmatrix.sync.aligned.m8n8.x4.trans.shared.b16 {%0,%1,%2,%3}, [%4];" \
                 : "=r"(r0), "=r"(r1), "=r"(r2), "=r"(r3) : "r"(addr))
#define HMMA16(acc, a, b0, b1) \
    asm volatile("mma.sync.aligned.m16n8k16.row.col.f32.f16.f16.f32 " \
                 "{%0,%1,%2,%3},{%4,%5,%6,%7},{%8,%9},{%0,%1,%2,%3};" \
                 : "+f"(acc[0]), "+f"(acc[1]), "+f"(acc[2]), "+f"(acc[3]) \
                 : "r"(a[0]), "r"(a[1]), "r"(a[2]), "r"(a[3]), "r"(b0), "r"(b1))

// ---------------- merged prep kernel ----------------
// z = 0..3: transpose+cvt W[z] into Wh[z]; z = 4: cvt X -> fp16
__global__ __launch_bounds__(256) void prep_kernel(
    const float4* __restrict__ X4,
    const float* __restrict__ W0, const float* __restrict__ W1,
    const float* __restrict__ W2, const float* __restrict__ W3,
    __half* __restrict__ Wh, uint2* __restrict__ Xh)
{
    const int z = blockIdx.z;
    if (z == 4) {
        int blk = blockIdx.y * 64 + blockIdx.x;
        int base = blk * 1024 + (threadIdx.y * 32 + threadIdx.x);
#pragma unroll
        for (int i = 0; i < 4; i++) {
            int idx = base + i * 256;
            float4 v = X4[idx];
            Xh[idx] = make_uint2(packh2(v.x, v.y), packh2(v.z, v.w));
        }
        return;
    }
    __shared__ float t[32][33];
    const float* W = (z == 0) ? W0 : (z == 1) ? W1 : (z == 2) ? W2 : W3;
    __half* dst = Wh + (size_t)z * DD;
    const int bx = blockIdx.x * 32;  // n
    const int by = blockIdx.y * 32;  // k
    const int tx = threadIdx.x, ty = threadIdx.y;
#pragma unroll
    for (int r = 0; r < 32; r += 8)
        t[ty + r][tx] = W[(size_t)(by + ty + r) * Dd + bx + tx];
    __syncthreads();
#pragma unroll
    for (int r = 0; r < 32; r += 8)
        dst[(size_t)(bx + ty + r) * Dd + by + tx] = __float2half_rn(t[tx][ty + r]);
}

// ---------------- fp16 GEMM: C[M,2048] = A[M,2048] @ Wt^T (frozen) ----------------
#define GBK 64
#define AST (128 * GBK * 2)      // 16384 B per operand
#define STB (2 * AST)            // 32768 B per stage
#define NST 3
#define SMEMT (NST * STB)        // 98304 B

__device__ __forceinline__ void hfill(
    const __half* __restrict__ A, const __half* __restrict__ Bt,
    uint32_t sbase, int stage, int m0, int n0, int k0, int tid)
{
    const uint32_t sA = sbase + stage * STB;
    const uint32_t sB = sA + AST;
#pragma unroll
    for (int i = 0; i < 4; i++) {
        int idx = tid + i * 256;
        int row = idx >> 3;
        int c   = idx & 7;
        uint32_t phys = row * 128 + ((c ^ (row & 7)) << 4);
        cp16(sA + phys, A + (size_t)(m0 + row) * Dd + k0 + c * 8);
    }
#pragma unroll
    for (int i = 0; i < 4; i++) {
        int idx = tid + i * 256;
        int row = idx >> 3;
        int c   = idx & 7;
        uint32_t phys = row * 128 + ((c ^ (row & 7)) << 4);
        cp16(sB + phys, Bt + (size_t)(n0 + row) * Dd + k0 + c * 8);
    }
}

__global__ __launch_bounds__(256, 2) void hgemm_kernel(
    const __half* __restrict__ A, const __half* __restrict__ Wh,
    void* C0, void* C1, void* C2, int out_f32)
{
    extern __shared__ char smem[];
    const uint32_t sbase = smem_u32(smem);
    const int tid  = threadIdx.x;
    const int wid  = tid >> 5;
    const int lane = tid & 31;
    const int g    = lane >> 2;
    const int t    = lane & 3;
    const int n0 = blockIdx.x * 128;
    const int m0 = blockIdx.y * 128;
    const int z  = blockIdx.z;

    const __half* Bt = Wh + (size_t)z * DD;
    void* Cv = (z == 0) ? C0 : ((z == 1) ? C1 : C2);

    const int warp_m = (wid & 3) * 32;
    const int warp_n = (wid >> 2) * 64;

    float acc[2][8][4];
#pragma unroll
    for (int i = 0; i < 2; i++)
#pragma unroll
        for (int j = 0; j < 8; j++)
#pragma unroll
            for (int c = 0; c < 4; c++) acc[i][j][c] = 0.f;

    hfill(A, Bt, sbase, 0, m0, n0, 0, tid);
    cp_commit();
    hfill(A, Bt, sbase, 1, m0, n0, GBK, tid);
    cp_commit();

    const int NCH = Dd / GBK;  // 32
    const int lrow_a = ((lane >> 3) & 1) * 8 + (lane & 7);
    const int lchk_a = (lane >> 4);
    const int lrow_b = ((lane >> 4) << 3) + (lane & 7);
    const int lchk_b = ((lane >> 3) & 1);

    for (int ch = 0; ch < NCH; ch++) {
        if (ch < NCH - 1) cp_wait<1>(); else cp_wait<0>();
        __syncthreads();

        if (ch + 2 < NCH) {
            hfill(A, Bt, sbase, (ch + 2) % NST, m0, n0, (ch + 2) * GBK, tid);
            cp_commit();
        }

        const uint32_t sA = sbase + (ch % NST) * STB;
        const uint32_t sB = sA + AST;

#pragma unroll
        for (int ks = 0; ks < 4; ks++) {
            const int c0 = ks * 2;

            uint32_t af[2][4];
#pragma unroll
            for (int wm = 0; wm < 2; wm++) {
                int row = warp_m + wm * 16 + lrow_a;
                int chk = c0 + lchk_a;
                uint32_t addr = sA + row * 128 + ((chk ^ (row & 7)) << 4);
                LDSM_X4(af[wm][0], af[wm][1], af[wm][2], af[wm][3], addr);
            }
#pragma unroll
            for (int p = 0; p < 4; p++) {
                int row = warp_n + p * 16 + lrow_b;
                int chk = c0 + lchk_b;
                uint32_t addr = sB + row * 128 + ((chk ^ (row & 7)) << 4);
                uint32_t b0, b1, b2, b3;
                LDSM_X4(b0, b1, b2, b3, addr);
#pragma unroll
                for (int wm = 0; wm < 2; wm++) {
                    HMMA16(acc[wm][2 * p],     af[wm], b0, b1);
                    HMMA16(acc[wm][2 * p + 1], af[wm], b2, b3);
                }
            }
        }
    }

    // ---- epilogue: smem-staged, fully coalesced 16B stores ----
    __syncthreads();
    if (out_f32) {
        float* stg = reinterpret_cast<float*>(smem);
#pragma unroll
        for (int wm = 0; wm < 2; wm++) {
            const int r0 = warp_m + wm * 16 + g;
#pragma unroll
            for (int wn = 0; wn < 8; wn++) {
                const int c = warp_n + wn * 8 + 2 * t;
                *reinterpret_cast<float2*>(&stg[r0 * 136 + c]) =
                    make_float2(acc[wm][wn][0], acc[wm][wn][1]);
                *reinterpret_cast<float2*>(&stg[(r0 + 8) * 136 + c]) =
                    make_float2(acc[wm][wn][2], acc[wm][wn][3]);
            }
        }
        __syncthreads();
        float* C = (float*)Cv;
#pragma unroll
        for (int i = 0; i < 16; i++) {
            int idx = tid + i * 256;
            int row = idx >> 5;
            int chk = idx & 31;
            uint4 v = *reinterpret_cast<const uint4*>(&stg[row * 136 + chk * 4]);
            *reinterpret_cast<uint4*>(&C[(size_t)(m0 + row) * Dd + n0 + chk * 4]) = v;
        }
    } else {
        __half* stg = reinterpret_cast<__half*>(smem);
#pragma unroll
        for (int wm = 0; wm < 2; wm++) {
            const int r0 = warp_m + wm * 16 + g;
#pragma unroll
            for (int wn = 0; wn < 8; wn++) {
                const int c = warp_n + wn * 8 + 2 * t;
                *reinterpret_cast<uint32_t*>(&stg[r0 * 136 + c]) =
                    packh2(acc[wm][wn][0], acc[wm][wn][1]);
                *reinterpret_cast<uint32_t*>(&stg[(r0 + 8) * 136 + c]) =
                    packh2(acc[wm][wn][2], acc[wm][wn][3]);
            }
        }
        __syncthreads();
        __half* C = (__half*)Cv;
#pragma unroll
        for (int i = 0; i < 8; i++) {
            int idx = tid + i * 256;
            int row = idx >> 4;
            int chk = idx & 15;
            uint4 v = *reinterpret_cast<const uint4*>(&stg[row * 136 + chk * 8]);
            *reinterpret_cast<uint4*>(&C[(size_t)(m0 + row) * Dd + n0 + chk * 8]) = v;
        }
    }
}

// ---------------- fp16 attention: 4 warps x 32 queries, 3 CTAs/SM ----------------
// 32-key sub-iterations shrink live registers (sacc 32, pa 16) to fit the
// 168-reg cap at occupancy 3. Arithmetic order identical to round 14/15.
#define AKS128  16384
#define AKST128 (2 * AKS128)     // 32 KB per stage
#define ASMEM   (2 * AKST128)    // 64 KB

__device__ __forceinline__ void afill128(
    const __half* __restrict__ K, const __half* __restrict__ V,
    uint32_t sbase, int stage, int b, int h, int kth, int ktw, int tid)
{
    const uint32_t sK = sbase + stage * AKST128;
    const uint32_t sV = sK + AKS128;
#pragma unroll
    for (int i = 0; i < 8; i++) {
        int idx = tid + i * 128;    // 0..1023
        int row = idx >> 3;         // token 0..127
        int c   = idx & 7;          // 16B chunk of hd
        int rr  = row >> 4;
        int cc  = row & 15;
        int skv = (kth * 8 + rr) * 64 + (ktw * 16 + cc);
        size_t gaddr = ((size_t)(b * Ss + skv)) * Dd + h * HDd + c * 8;
        uint32_t phys = row * 128 + ((c ^ (row & 7)) << 4);
        cp16(sK + phys, K + gaddr);
        cp16(sV + phys, V + gaddr);
    }
}

__global__ __launch_bounds__(128, 3) void attn_h_kernel(
    const __half* __restrict__ Q, const __half* __restrict__ Kh,
    const __half* __restrict__ Vh, __half* __restrict__ O)
{
    extern __shared__ char asmem[];
    const uint32_t sbase = smem_u32(asmem);

    const int tile = blockIdx.x;
    const int h    = blockIdx.y;
    const int b    = blockIdx.z;
    const int tid  = threadIdx.x;
    const int wid  = tid >> 5;
    const int lane = tid & 31;
    const int g    = lane >> 2;
    const int tg   = lane & 3;

    const int th_i = tile >> 2;
    const int tw_i = tile & 3;

    const int chc = min(max(th_i, 1), NTH - 1);
    const int cwc = min(max(tw_i, 1), NTW - 1);
    int kvt[4];
    kvt[0] = (chc - 1) * NTW + (cwc - 1);
    kvt[1] = (chc - 1) * NTW + cwc;
    kvt[2] = chc * NTW + (cwc - 1);
    kvt[3] = chc * NTW + cwc;

    // prologue fill (tile 0) first, so Q loads overlap it
    afill128(Kh, Vh, sbase, 0, b, h, kvt[0] >> 2, kvt[0] & 3, tid);
    cp_commit();

    // warp owns 32 queries = two m16 tiles
    size_t qrow[2][2];
#pragma unroll
    for (int mt = 0; mt < 2; mt++) {
        int qi0 = wid * 32 + mt * 16 + g;
        int qi1 = qi0 + 8;
        int sq0 = (th_i * 8 + (qi0 >> 4)) * 64 + tw_i * 16 + (qi0 & 15);
        int sq1 = (th_i * 8 + (qi1 >> 4)) * 64 + tw_i * 16 + (qi1 & 15);
        qrow[mt][0] = ((size_t)(b * Ss + sq0)) * Dd + h * HDd;
        qrow[mt][1] = ((size_t)(b * Ss + sq1)) * Dd + h * HDd;
    }

    const __half2 qscale = __floats2half2_rn(0.125f, 0.125f);
    uint32_t qa[2][4][4];
#pragma unroll
    for (int mt = 0; mt < 2; mt++)
#pragma unroll
        for (int ks = 0; ks < 4; ks++) {
            int kb = ks * 16;
            __half2 v0 = *reinterpret_cast<const __half2*>(&Q[qrow[mt][0] + kb + 2 * tg]);
            __half2 v1 = *reinterpret_cast<const __half2*>(&Q[qrow[mt][1] + kb + 2 * tg]);
            __half2 v2 = *reinterpret_cast<const __half2*>(&Q[qrow[mt][0] + kb + 8 + 2 * tg]);
            __half2 v3 = *reinterpret_cast<const __half2*>(&Q[qrow[mt][1] + kb + 8 + 2 * tg]);
            v0 = __hmul2(v0, qscale); v1 = __hmul2(v1, qscale);
            v2 = __hmul2(v2, qscale); v3 = __hmul2(v3, qscale);
            qa[mt][ks][0] = *reinterpret_cast<uint32_t*>(&v0);
            qa[mt][ks][1] = *reinterpret_cast<uint32_t*>(&v1);
            qa[mt][ks][2] = *reinterpret_cast<uint32_t*>(&v2);
            qa[mt][ks][3] = *reinterpret_cast<uint32_t*>(&v3);
        }

    float oacc[2][8][4];
#pragma unroll
    for (int mt = 0; mt < 2; mt++)
#pragma unroll
        for (int j = 0; j < 8; j++)
#pragma unroll
            for (int c = 0; c < 4; c++) oacc[mt][j][c] = 0.f;
    float lacc[2][4] = {{0.f,0.f,0.f,0.f},{0.f,0.f,0.f,0.f}};
    const uint32_t ones2 = 0x3C003C00u;

    const int lrow_b = ((lane >> 4) << 3) + (lane & 7);
    const int lchk_b = ((lane >> 3) & 1);
    const int lrow_v = ((lane >> 3) & 1) * 8 + (lane & 7);
    const int lchk_v = (lane >> 4);
    const float L2E = 1.4426950408889634f;

    for (int c4 = 0; c4 < 4; c4++) {
        cp_wait<0>();
        __syncthreads();

        if (c4 + 1 < 4) {
            int kt = kvt[c4 + 1];
            afill128(Kh, Vh, sbase, (c4 + 1) & 1, b, h, kt >> 2, kt & 3, tid);
            cp_commit();
        }

        const uint32_t sK = sbase + (c4 & 1) * AKST128;
        const uint32_t sV = sK + AKS128;

#pragma unroll
        for (int h2 = 0; h2 < 2; h2++) {
            const int rb = h2 * 64;

#pragma unroll
            for (int sub = 0; sub < 2; sub++) {
                // ---- S = Q K^T over keys [rb+32sub, rb+32sub+32) ----
                float sacc[2][4][4];
#pragma unroll
                for (int mt = 0; mt < 2; mt++)
#pragma unroll
                    for (int j = 0; j < 4; j++)
#pragma unroll
                        for (int c = 0; c < 4; c++) sacc[mt][j][c] = 0.f;

#pragma unroll
                for (int ks = 0; ks < 4; ks++) {
                    const int c0 = ks * 2;
#pragma unroll
                    for (int pp = 0; pp < 2; pp++) {
                        int p = sub * 2 + pp;
                        int row = rb + p * 16 + lrow_b;
                        int chk = c0 + lchk_b;
                        uint32_t addr = sK + row * 128 + ((chk ^ (row & 7)) << 4);
                        uint32_t k0, k1, k2, k3;
                        LDSM_X4(k0, k1, k2, k3, addr);
#pragma unroll
                        for (int mt = 0; mt < 2; mt++) {
                            HMMA16(sacc[mt][2 * pp],     qa[mt][ks], k0, k1);
                            HMMA16(sacc[mt][2 * pp + 1], qa[mt][ks], k2, k3);
                        }
                    }
                }

                // ---- p = exp(s) via f16x2 ex2; l via P @ ones HMMA ----
                uint32_t pa[2][2][4];
#pragma unroll
                for (int mt = 0; mt < 2; mt++)
#pragma unroll
                    for (int mj = 0; mj < 2; mj++) {
                        pa[mt][mj][0] = packh2(sacc[mt][2 * mj][0] * L2E,     sacc[mt][2 * mj][1] * L2E);
                        pa[mt][mj][1] = packh2(sacc[mt][2 * mj][2] * L2E,     sacc[mt][2 * mj][3] * L2E);
                        pa[mt][mj][2] = packh2(sacc[mt][2 * mj + 1][0] * L2E, sacc[mt][2 * mj + 1][1] * L2E);
                        pa[mt][mj][3] = packh2(sacc[mt][2 * mj + 1][2] * L2E, sacc[mt][2 * mj + 1][3] * L2E);
                        asm("ex2.approx.f16x2 %0, %0;" : "+r"(pa[mt][mj][0]));
                        asm("ex2.approx.f16x2 %0, %0;" : "+r"(pa[mt][mj][1]));
                        asm("ex2.approx.f16x2 %0, %0;" : "+r"(pa[mt][mj][2]));
                        asm("ex2.approx.f16x2 %0, %0;" : "+r"(pa[mt][mj][3]));
                        HMMA16(lacc[mt], pa[mt][mj], ones2, ones2);
                    }

                // ---- O += P V over the same 32 keys ----
#pragma unroll
                for (int mj = 0; mj < 2; mj++) {
                    const int kb = rb + (sub * 2 + mj) * 16;
#pragma unroll
                    for (int p = 0; p < 4; p++) {
                        int row = kb + lrow_v;
                        int chk = 2 * p + lchk_v;
                        uint32_t addr = sV + row * 128 + ((chk ^ (row & 7)) << 4);
                        uint32_t v0, v1, v2, v3;
                        LDSM_X4_T(v0, v1, v2, v3, addr);
#pragma unroll
                        for (int mt = 0; mt < 2; mt++) {
                            HMMA16(oacc[mt][2 * p],     pa[mt][mj], v0, v1);
                            HMMA16(oacc[mt][2 * p + 1], pa[mt][mj], v2, v3);
                        }
                    }
                }
            }
        }
    }

    // ---- epilogue ----
#pragma unroll
    for (int mt = 0; mt < 2; mt++) {
        const float inv0 = 1.f / lacc[mt][0];
        const float inv1 = 1.f / lacc[mt][2];
#pragma unroll
        for (int jn = 0; jn < 8; jn++) {
            int vd = 8 * jn + 2 * tg;
            *reinterpret_cast<uint32_t*>(&O[qrow[mt][0] + vd]) =
                packh2(oacc[mt][jn][0] * inv0, oacc[mt][jn][1] * inv0);
            *reinterpret_cast<uint32_t*>(&O[qrow[mt][1] + vd]) =
                packh2(oacc[mt][jn][2] * inv1, oacc[mt][jn][3] * inv1);
        }
    }
}

// ---------------- launch ----------------
extern "C" void kernel_launch(void* const* d_in, const int* in_sizes, int n_in,
                              void* d_out, int out_size)
{
    const float* X  = (const float*)d_in[0];
    const float* Wq = (const float*)d_in[1];
    const float* Wk = (const float*)d_in[2];
    const float* Wv = (const float*)d_in[3];
    const float* Wo = (const float*)d_in[4];
    float* out = (float*)d_out;

    __half *Qh, *Kh, *Vh, *Oh, *Xh, *Wh;
    cudaGetSymbolAddress((void**)&Qh, g_Qh);
    cudaGetSymbolAddress((void**)&Kh, g_Kh);
    cudaGetSymbolAddress((void**)&Vh, g_Vh);
    cudaGetSymbolAddress((void**)&Oh, g_Oh);
    cudaGetSymbolAddress((void**)&Xh, g_Xh);
    cudaGetSymbolAddress((void**)&Wh, g_Wh);

    cudaFuncSetAttribute(hgemm_kernel,
                         cudaFuncAttributeMaxDynamicSharedMemorySize, SMEMT);
    cudaFuncSetAttribute(attn_h_kernel,
                         cudaFuncAttributeMaxDynamicSharedMemorySize, ASMEM);

    // merged prep: 4 weight transposes + X convert in one launch
    dim3 tb(32, 8), tg5(64, 64, 5);
    prep_kernel<<<tg5, tb>>>((const float4*)X, Wq, Wk, Wv, Wo, Wh, (uint2*)Xh);

    // fused Q/K/V projections (fp16 out)
    dim3 gq(Dd / 128, MM / 128, 3);
    hgemm_kernel<<<gq, 256, SMEMT>>>(Xh, Wh, Qh, Kh, Vh, 0);

    dim3 ga(32, Hh, Bb);
    attn_h_kernel<<<ga, 128, ASMEM>>>(Qh, Kh, Vh, Oh);

    // output projection (fp32 out)
    dim3 gg(Dd / 128, MM / 128, 1);
    hgemm_kernel<<<gg, 256, SMEMT>>>(Oh, Wh + 3 * DD, out, out, out, 1);
}

// round 17
// speedup vs baseline: 1.0185x; 1.0097x over previous
#include <cuda_runtime.h>
#include <cuda_fp16.h>
#include <stdint.h>

// ---------------- static geometry ----------------
#define Bb   2
#define Ss   4096
#define Dd   2048
#define Hh   32
#define HDd  64
#define NTH  8
#define NTW  4

#define MM   (Bb*Ss)  // 8192
#define DD   ((size_t)Dd * Dd)

// ---------------- scratch (fp16) ----------------
__device__ __half g_Qh[(size_t)MM * Dd];
__device__ __half g_Kh[(size_t)MM * Dd];
__device__ __half g_Vh[(size_t)MM * Dd];
__device__ __half g_Oh[(size_t)MM * Dd];
__device__ __half g_Xh[(size_t)MM * Dd];
__device__ __half g_Wh[4 * DD];          // transposed fp16 weights [N][K]

// ---------------- helpers ----------------
__device__ __forceinline__ uint32_t smem_u32(const void* p) {
    uint32_t a;
    asm("{ .reg .u64 t; cvta.to.shared.u64 t, %1; cvt.u32.u64 %0, t; }"
        : "=r"(a) : "l"(p));
    return a;
}
__device__ __forceinline__ void cp16(uint32_t dst, const void* src) {
    asm volatile("cp.async.cg.shared.global [%0], [%1], 16;"
                 :: "r"(dst), "l"(src) : "memory");
}
__device__ __forceinline__ void cp_commit() {
    asm volatile("cp.async.commit_group;" ::: "memory");
}
template<int N>
__device__ __forceinline__ void cp_wait() {
    asm volatile("cp.async.wait_group %0;" :: "n"(N) : "memory");
}
__device__ __forceinline__ uint32_t packh2(float a, float b) {
    __half2 h = __floats2half2_rn(a, b);
    return *reinterpret_cast<uint32_t*>(&h);
}

#define LDSM_X4(r0, r1, r2, r3, addr) \
    asm volatile("ldmatrix.sync.aligned.m8n8.x4.shared.b16 {%0,%1,%2,%3}, [%4];" \
                 : "=r"(r0), "=r"(r1), "=r"(r2), "=r"(r3) : "r"(addr))
#define LDSM_X4_T(r0, r1, r2, r3, addr) \
    asm volatile("ldmatrix.sync.aligned.m8n8.x4.trans.shared.b16 {%0,%1,%2,%3}, [%4];" \
                 : "=r"(r0), "=r"(r1), "=r"(r2), "=r"(r3) : "r"(addr))
#define HMMA16(acc, a, b0, b1) \
    asm volatile("mma.sync.aligned.m16n8k16.row.col.f32.f16.f16.f32 " \
                 "{%0,%1,%2,%3},{%4,%5,%6,%7},{%8,%9},{%0,%1,%2,%3};" \
                 : "+f"(acc[0]), "+f"(acc[1]), "+f"(acc[2]), "+f"(acc[3]) \
                 : "r"(a[0]), "r"(a[1]), "r"(a[2]), "r"(a[3]), "r"(b0), "r"(b1))

// ---------------- merged prep kernel ----------------
__global__ __launch_bounds__(256) void prep_kernel(
    const float4* __restrict__ X4,
    const float* __restrict__ W0, const float* __restrict__ W1,
    const float* __restrict__ W2, const float* __restrict__ W3,
    __half* __restrict__ Wh, uint2* __restrict__ Xh)
{
    const int z = blockIdx.z;
    if (z == 4) {
        int blk = blockIdx.y * 64 + blockIdx.x;
        int base = blk * 1024 + (threadIdx.y * 32 + threadIdx.x);
#pragma unroll
        for (int i = 0; i < 4; i++) {
            int idx = base + i * 256;
            float4 v = X4[idx];
            Xh[idx] = make_uint2(packh2(v.x, v.y), packh2(v.z, v.w));
        }
        return;
    }
    __shared__ float t[32][33];
    const float* W = (z == 0) ? W0 : (z == 1) ? W1 : (z == 2) ? W2 : W3;
    __half* dst = Wh + (size_t)z * DD;
    const int bx = blockIdx.x * 32;  // n
    const int by = blockIdx.y * 32;  // k
    const int tx = threadIdx.x, ty = threadIdx.y;
#pragma unroll
    for (int r = 0; r < 32; r += 8)
        t[ty + r][tx] = W[(size_t)(by + ty + r) * Dd + bx + tx];
    __syncthreads();
#pragma unroll
    for (int r = 0; r < 32; r += 8)
        dst[(size_t)(bx + ty + r) * Dd + by + tx] = __float2half_rn(t[tx][ty + r]);
}

// ---------------- fp16 GEMM: C[M,2048] = A[M,2048] @ Wt^T ----------------
// Barrier-in-tensor-shadow mainloop: sync moved to the bottom of each
// iteration so the trailing HMMA batch hides the rendezvous.
#define GBK 64
#define AST (128 * GBK * 2)      // 16384 B per operand
#define STB (2 * AST)            // 32768 B per stage
#define NST 3
#define SMEMT (NST * STB)        // 98304 B

__device__ __forceinline__ void hfill(
    const __half* __restrict__ A, const __half* __restrict__ Bt,
    uint32_t sbase, int stage, int m0, int n0, int k0, int tid)
{
    const uint32_t sA = sbase + stage * STB;
    const uint32_t sB = sA + AST;
#pragma unroll
    for (int i = 0; i < 4; i++) {
        int idx = tid + i * 256;
        int row = idx >> 3;
        int c   = idx & 7;
        uint32_t phys = row * 128 + ((c ^ (row & 7)) << 4);
        cp16(sA + phys, A + (size_t)(m0 + row) * Dd + k0 + c * 8);
    }
#pragma unroll
    for (int i = 0; i < 4; i++) {
        int idx = tid + i * 256;
        int row = idx >> 3;
        int c   = idx & 7;
        uint32_t phys = row * 128 + ((c ^ (row & 7)) << 4);
        cp16(sB + phys, Bt + (size_t)(n0 + row) * Dd + k0 + c * 8);
    }
}

__global__ __launch_bounds__(256, 2) void hgemm_kernel(
    const __half* __restrict__ A, const __half* __restrict__ Wh,
    void* C0, void* C1, void* C2, int out_f32)
{
    extern __shared__ char smem[];
    const uint32_t sbase = smem_u32(smem);
    const int tid  = threadIdx.x;
    const int wid  = tid >> 5;
    const int lane = tid & 31;
    const int g    = lane >> 2;
    const int t    = lane & 3;
    const int n0 = blockIdx.x * 128;
    const int m0 = blockIdx.y * 128;
    const int z  = blockIdx.z;

    const __half* Bt = Wh + (size_t)z * DD;
    void* Cv = (z == 0) ? C0 : ((z == 1) ? C1 : C2);

    const int warp_m = (wid & 3) * 32;
    const int warp_n = (wid >> 2) * 64;

    float acc[2][8][4];
#pragma unroll
    for (int i = 0; i < 2; i++)
#pragma unroll
        for (int j = 0; j < 8; j++)
#pragma unroll
            for (int c = 0; c < 4; c++) acc[i][j][c] = 0.f;

    // prologue: stages 0,1 in flight; publish stage 0
    hfill(A, Bt, sbase, 0, m0, n0, 0, tid);
    cp_commit();
    hfill(A, Bt, sbase, 1, m0, n0, GBK, tid);
    cp_commit();
    cp_wait<1>();
    __syncthreads();   // stage 0 visible to all

    const int NCH = Dd / GBK;  // 32
    const int lrow_a = ((lane >> 3) & 1) * 8 + (lane & 7);
    const int lchk_a = (lane >> 4);
    const int lrow_b = ((lane >> 4) << 3) + (lane & 7);
    const int lchk_b = ((lane >> 3) & 1);

    for (int ch = 0; ch < NCH; ch++) {
        // fill two ahead (stage being overwritten was published-safe by
        // the barrier at the END of the previous iteration)
        if (ch + 2 < NCH) {
            hfill(A, Bt, sbase, (ch + 2) % NST, m0, n0, (ch + 2) * GBK, tid);
            cp_commit();
        }

        const uint32_t sA = sbase + (ch % NST) * STB;
        const uint32_t sB = sA + AST;

#pragma unroll
        for (int ks = 0; ks < 4; ks++) {
            const int c0 = ks * 2;

            uint32_t af[2][4];
#pragma unroll
            for (int wm = 0; wm < 2; wm++) {
                int row = warp_m + wm * 16 + lrow_a;
                int chk = c0 + lchk_a;
                uint32_t addr = sA + row * 128 + ((chk ^ (row & 7)) << 4);
                LDSM_X4(af[wm][0], af[wm][1], af[wm][2], af[wm][3], addr);
            }
#pragma unroll
            for (int p = 0; p < 4; p++) {
                int row = warp_n + p * 16 + lrow_b;
                int chk = c0 + lchk_b;
                uint32_t addr = sB + row * 128 + ((chk ^ (row & 7)) << 4);
                uint32_t b0, b1, b2, b3;
                LDSM_X4(b0, b1, b2, b3, addr);
#pragma unroll
                for (int wm = 0; wm < 2; wm++) {
                    HMMA16(acc[wm][2 * p],     af[wm], b0, b1);
                    HMMA16(acc[wm][2 * p + 1], af[wm], b2, b3);
                }
            }
        }

        // bottom-of-loop publish: bar sits in the shadow of the HMMA tail
        if (ch < NCH - 1) {
            if (ch < NCH - 2) cp_wait<1>(); else cp_wait<0>();
            __syncthreads();   // publish stage ch+1; licenses fill(ch+3)
        }
    }

    // ---- epilogue: smem-staged, fully coalesced 16B stores ----
    __syncthreads();
    if (out_f32) {
        float* stg = reinterpret_cast<float*>(smem);
#pragma unroll
        for (int wm = 0; wm < 2; wm++) {
            const int r0 = warp_m + wm * 16 + g;
#pragma unroll
            for (int wn = 0; wn < 8; wn++) {
                const int c = warp_n + wn * 8 + 2 * t;
                *reinterpret_cast<float2*>(&stg[r0 * 136 + c]) =
                    make_float2(acc[wm][wn][0], acc[wm][wn][1]);
                *reinterpret_cast<float2*>(&stg[(r0 + 8) * 136 + c]) =
                    make_float2(acc[wm][wn][2], acc[wm][wn][3]);
            }
        }
        __syncthreads();
        float* C = (float*)Cv;
#pragma unroll
        for (int i = 0; i < 16; i++) {
            int idx = tid + i * 256;
            int row = idx >> 5;
            int chk = idx & 31;
            uint4 v = *reinterpret_cast<const uint4*>(&stg[row * 136 + chk * 4]);
            *reinterpret_cast<uint4*>(&C[(size_t)(m0 + row) * Dd + n0 + chk * 4]) = v;
        }
    } else {
        __half* stg = reinterpret_cast<__half*>(smem);
#pragma unroll
        for (int wm = 0; wm < 2; wm++) {
            const int r0 = warp_m + wm * 16 + g;
#pragma unroll
            for (int wn = 0; wn < 8; wn++) {
                const int c = warp_n + wn * 8 + 2 * t;
                *reinterpret_cast<uint32_t*>(&stg[r0 * 136 + c]) =
                    packh2(acc[wm][wn][0], acc[wm][wn][1]);
                *reinterpret_cast<uint32_t*>(&stg[(r0 + 8) * 136 + c]) =
                    packh2(acc[wm][wn][2], acc[wm][wn][3]);
            }
        }
        __syncthreads();
        __half* C = (__half*)Cv;
#pragma unroll
        for (int i = 0; i < 8; i++) {
            int idx = tid + i * 256;
            int row = idx >> 4;
            int chk = idx & 15;
            uint4 v = *reinterpret_cast<const uint4*>(&stg[row * 136 + chk * 8]);
            *reinterpret_cast<uint4*>(&C[(size_t)(m0 + row) * Dd + n0 + chk * 8]) = v;
        }
    }
}

// ---------------- fp16 attention: 4 warps x 32 queries, 3 CTAs/SM ----------------
// Same barrier-in-tensor-shadow restructure: the PV HMMA tail hides the bar.
#define AKS128  16384
#define AKST128 (2 * AKS128)     // 32 KB per stage
#define ASMEM   (2 * AKST128)    // 64 KB

__device__ __forceinline__ void afill128(
    const __half* __restrict__ K, const __half* __restrict__ V,
    uint32_t sbase, int stage, int b, int h, int kth, int ktw, int tid)
{
    const uint32_t sK = sbase + stage * AKST128;
    const uint32_t sV = sK + AKS128;
#pragma unroll
    for (int i = 0; i < 8; i++) {
        int idx = tid + i * 128;    // 0..1023
        int row = idx >> 3;         // token 0..127
        int c   = idx & 7;          // 16B chunk of hd
        int rr  = row >> 4;
        int cc  = row & 15;
        int skv = (kth * 8 + rr) * 64 + (ktw * 16 + cc);
        size_t gaddr = ((size_t)(b * Ss + skv)) * Dd + h * HDd + c * 8;
        uint32_t phys = row * 128 + ((c ^ (row & 7)) << 4);
        cp16(sK + phys, K + gaddr);
        cp16(sV + phys, V + gaddr);
    }
}

__global__ __launch_bounds__(128, 3) void attn_h_kernel(
    const __half* __restrict__ Q, const __half* __restrict__ Kh,
    const __half* __restrict__ Vh, __half* __restrict__ O)
{
    extern __shared__ char asmem[];
    const uint32_t sbase = smem_u32(asmem);

    const int tile = blockIdx.x;
    const int h    = blockIdx.y;
    const int b    = blockIdx.z;
    const int tid  = threadIdx.x;
    const int wid  = tid >> 5;
    const int lane = tid & 31;
    const int g    = lane >> 2;
    const int tg   = lane & 3;

    const int th_i = tile >> 2;
    const int tw_i = tile & 3;

    const int chc = min(max(th_i, 1), NTH - 1);
    const int cwc = min(max(tw_i, 1), NTW - 1);
    int kvt[4];
    kvt[0] = (chc - 1) * NTW + (cwc - 1);
    kvt[1] = (chc - 1) * NTW + cwc;
    kvt[2] = chc * NTW + (cwc - 1);
    kvt[3] = chc * NTW + cwc;

    // prologue fill (tile 0) first, so Q loads overlap it
    afill128(Kh, Vh, sbase, 0, b, h, kvt[0] >> 2, kvt[0] & 3, tid);
    cp_commit();

    // warp owns 32 queries = two m16 tiles
    size_t qrow[2][2];
#pragma unroll
    for (int mt = 0; mt < 2; mt++) {
        int qi0 = wid * 32 + mt * 16 + g;
        int qi1 = qi0 + 8;
        int sq0 = (th_i * 8 + (qi0 >> 4)) * 64 + tw_i * 16 + (qi0 & 15);
        int sq1 = (th_i * 8 + (qi1 >> 4)) * 64 + tw_i * 16 + (qi1 & 15);
        qrow[mt][0] = ((size_t)(b * Ss + sq0)) * Dd + h * HDd;
        qrow[mt][1] = ((size_t)(b * Ss + sq1)) * Dd + h * HDd;
    }

    const __half2 qscale = __floats2half2_rn(0.125f, 0.125f);
    uint32_t qa[2][4][4];
#pragma unroll
    for (int mt = 0; mt < 2; mt++)
#pragma unroll
        for (int ks = 0; ks < 4; ks++) {
            int kb = ks * 16;
            __half2 v0 = *reinterpret_cast<const __half2*>(&Q[qrow[mt][0] + kb + 2 * tg]);
            __half2 v1 = *reinterpret_cast<const __half2*>(&Q[qrow[mt][1] + kb + 2 * tg]);
            __half2 v2 = *reinterpret_cast<const __half2*>(&Q[qrow[mt][0] + kb + 8 + 2 * tg]);
            __half2 v3 = *reinterpret_cast<const __half2*>(&Q[qrow[mt][1] + kb + 8 + 2 * tg]);
            v0 = __hmul2(v0, qscale); v1 = __hmul2(v1, qscale);
            v2 = __hmul2(v2, qscale); v3 = __hmul2(v3, qscale);
            qa[mt][ks][0] = *reinterpret_cast<uint32_t*>(&v0);
            qa[mt][ks][1] = *reinterpret_cast<uint32_t*>(&v1);
            qa[mt][ks][2] = *reinterpret_cast<uint32_t*>(&v2);
            qa[mt][ks][3] = *reinterpret_cast<uint32_t*>(&v3);
        }

    float oacc[2][8][4];
#pragma unroll
    for (int mt = 0; mt < 2; mt++)
#pragma unroll
        for (int j = 0; j < 8; j++)
#pragma unroll
            for (int c = 0; c < 4; c++) oacc[mt][j][c] = 0.f;
    float lacc[2][4] = {{0.f,0.f,0.f,0.f},{0.f,0.f,0.f,0.f}};
    const uint32_t ones2 = 0x3C003C00u;

    const int lrow_b = ((lane >> 4) << 3) + (lane & 7);
    const int lchk_b = ((lane >> 3) & 1);
    const int lrow_v = ((lane >> 3) & 1) * 8 + (lane & 7);
    const int lchk_v = (lane >> 4);
    const float L2E = 1.4426950408889634f;

    // publish stage 0
    cp_wait<0>();
    __syncthreads();

    for (int c4 = 0; c4 < 4; c4++) {
        // fill next tile (stage being overwritten was freed by the barrier
        // at the END of the previous iteration)
        if (c4 + 1 < 4) {
            int kt = kvt[c4 + 1];
            afill128(Kh, Vh, sbase, (c4 + 1) & 1, b, h, kt >> 2, kt & 3, tid);
            cp_commit();
        }

        const uint32_t sK = sbase + (c4 & 1) * AKST128;
        const uint32_t sV = sK + AKS128;

#pragma unroll
        for (int h2 = 0; h2 < 2; h2++) {
            const int rb = h2 * 64;

#pragma unroll
            for (int sub = 0; sub < 2; sub++) {
                float sacc[2][4][4];
#pragma unroll
                for (int mt = 0; mt < 2; mt++)
#pragma unroll
                    for (int j = 0; j < 4; j++)
#pragma unroll
                        for (int c = 0; c < 4; c++) sacc[mt][j][c] = 0.f;

#pragma unroll
                for (int ks = 0; ks < 4; ks++) {
                    const int c0 = ks * 2;
#pragma unroll
                    for (int pp = 0; pp < 2; pp++) {
                        int p = sub * 2 + pp;
                        int row = rb + p * 16 + lrow_b;
                        int chk = c0 + lchk_b;
                        uint32_t addr = sK + row * 128 + ((chk ^ (row & 7)) << 4);
                        uint32_t k0, k1, k2, k3;
                        LDSM_X4(k0, k1, k2, k3, addr);
#pragma unroll
                        for (int mt = 0; mt < 2; mt++) {
                            HMMA16(sacc[mt][2 * pp],     qa[mt][ks], k0, k1);
                            HMMA16(sacc[mt][2 * pp + 1], qa[mt][ks], k2, k3);
                        }
                    }
                }

                uint32_t pa[2][2][4];
#pragma unroll
                for (int mt = 0; mt < 2; mt++)
#pragma unroll
                    for (int mj = 0; mj < 2; mj++) {
                        pa[mt][mj][0] = packh2(sacc[mt][2 * mj][0] * L2E,     sacc[mt][2 * mj][1] * L2E);
                        pa[mt][mj][1] = packh2(sacc[mt][2 * mj][2] * L2E,     sacc[mt][2 * mj][3] * L2E);
                        pa[mt][mj][2] = packh2(sacc[mt][2 * mj + 1][0] * L2E, sacc[mt][2 * mj + 1][1] * L2E);
                        pa[mt][mj][3] = packh2(sacc[mt][2 * mj + 1][2] * L2E, sacc[mt][2 * mj + 1][3] * L2E);
                        asm("ex2.approx.f16x2 %0, %0;" : "+r"(pa[mt][mj][0]));
                        asm("ex2.approx.f16x2 %0, %0;" : "+r"(pa[mt][mj][1]));
                        asm("ex2.approx.f16x2 %0, %0;" : "+r"(pa[mt][mj][2]));
                        asm("ex2.approx.f16x2 %0, %0;" : "+r"(pa[mt][mj][3]));
                        HMMA16(lacc[mt], pa[mt][mj], ones2, ones2);
                    }

#pragma unroll
                for (int mj = 0; mj < 2; mj++) {
                    const int kb = rb + (sub * 2 + mj) * 16;
#pragma unroll
                    for (int p = 0; p < 4; p++) {
                        int row = kb + lrow_v;
                        int chk = 2 * p + lchk_v;
                        uint32_t addr = sV + row * 128 + ((chk ^ (row & 7)) << 4);
                        uint32_t v0, v1, v2, v3;
                        LDSM_X4_T(v0, v1, v2, v3, addr);
#pragma unroll
                        for (int mt = 0; mt < 2; mt++) {
                            HMMA16(oacc[mt][2 * p],     pa[mt][mj], v0, v1);
                            HMMA16(oacc[mt][2 * p + 1], pa[mt][mj], v2, v3);
                        }
                    }
                }
            }
        }

        // bottom-of-loop publish: bar hidden under the PV HMMA tail
        if (c4 < 3) {
            cp_wait<0>();
            __syncthreads();
        }
    }

    // ---- epilogue ----
#pragma unroll
    for (int mt = 0; mt < 2; mt++) {
        const float inv0 = 1.f / lacc[mt][0];
        const float inv1 = 1.f / lacc[mt][2];
#pragma unroll
        for (int jn = 0; jn < 8; jn++) {
            int vd = 8 * jn + 2 * tg;
            *reinterpret_cast<uint32_t*>(&O[qrow[mt][0] + vd]) =
                packh2(oacc[mt][jn][0] * inv0, oacc[mt][jn][1] * inv0);
            *reinterpret_cast<uint32_t*>(&O[qrow[mt][1] + vd]) =
                packh2(oacc[mt][jn][2] * inv1, oacc[mt][jn][3] * inv1);
        }
    }
}

// ---------------- launch ----------------
extern "C" void kernel_launch(void* const* d_in, const int* in_sizes, int n_in,
                              void* d_out, int out_size)
{
    const float* X  = (const float*)d_in[0];
    const float* Wq = (const float*)d_in[1];
    const float* Wk = (const float*)d_in[2];
    const float* Wv = (const float*)d_in[3];
    const float* Wo = (const float*)d_in[4];
    float* out = (float*)d_out;

    __half *Qh, *Kh, *Vh, *Oh, *Xh, *Wh;
    cudaGetSymbolAddress((void**)&Qh, g_Qh);
    cudaGetSymbolAddress((void**)&Kh, g_Kh);
    cudaGetSymbolAddress((void**)&Vh, g_Vh);
    cudaGetSymbolAddress((void**)&Oh, g_Oh);
    cudaGetSymbolAddress((void**)&Xh, g_Xh);
    cudaGetSymbolAddress((void**)&Wh, g_Wh);

    cudaFuncSetAttribute(hgemm_kernel,
                         cudaFuncAttributeMaxDynamicSharedMemorySize, SMEMT);
    cudaFuncSetAttribute(attn_h_kernel,
                         cudaFuncAttributeMaxDynamicSharedMemorySize, ASMEM);

    // merged prep: 4 weight transposes + X convert in one launch
    dim3 tb(32, 8), tg5(64, 64, 5);
    prep_kernel<<<tg5, tb>>>((const float4*)X, Wq, Wk, Wv, Wo, Wh, (uint2*)Xh);

    // fused Q/K/V projections (fp16 out)
    dim3 gq(Dd / 128, MM / 128, 3);
    hgemm_kernel<<<gq, 256, SMEMT>>>(Xh, Wh, Qh, Kh, Vh, 0);

    dim3 ga(32, Hh, Bb);
    attn_h_kernel<<<ga, 128, ASMEM>>>(Qh, Kh, Vh, Oh);

    // output projection (fp32 out)
    dim3 gg(Dd / 128, MM / 128, 1);
    hgemm_kernel<<<gg, 256, SMEMT>>>(Oh, Wh + 3 * DD, out, out, out, 1);
}